// round 3
// baseline (speedup 1.0000x reference)
#include <cuda_runtime.h>
#include <stdint.h>

#define NN 50000
#define NE 800000
#define IN_DIM 96
#define HID 32
#define OUT_DIM 64

#define SCAN_BS 1024
#define SCAN_CHUNK 4096            // 4 items/thread
#define NBLK ((NN + SCAN_CHUNK - 1) / SCAN_CHUNK)   // 13

// ---------------- scratch (device globals; no allocation allowed) ----------
__device__ __align__(16) float g_y1[NN * HID];    // x @ W1l (aggregated source)
__device__ __align__(16) float g_z1[NN * HID];    // x @ W1r (self term)
__device__ __align__(16) float g_h[NN * HID];     // hidden activations
__device__ __align__(16) float g_v[NN * HID];     // layer-2 mean agg (pre-scaled)
__device__ float g_invc[NN];
__device__ int g_deg[NN];
__device__ int g_rowptr[NN + 1];
__device__ int g_cursor[NN];
__device__ int g_srcs[NE];
__device__ int g_partials[NBLK];
__device__ int g_blockoff[NBLK];

// ================= CSR build =================
__global__ void zero_deg() {
    int i = blockIdx.x * blockDim.x + threadIdx.x;
    if (i < NN) g_deg[i] = 0;
}

__global__ void hist_kernel(const int* __restrict__ dst, int E) {
    int e = blockIdx.x * blockDim.x + threadIdx.x;
    if (e < E) atomicAdd(&g_deg[dst[e]], 1);
}

__global__ void __launch_bounds__(SCAN_BS) scan_partial() {
    int b = blockIdx.x, t = threadIdx.x;
    int lane = t & 31, warp = t >> 5;
    int base = b * SCAN_CHUNK + t * 4;
    int s = 0;
#pragma unroll
    for (int j = 0; j < 4; j++)
        if (base + j < NN) s += g_deg[base + j];
    // block reduce
#pragma unroll
    for (int o = 16; o > 0; o >>= 1) s += __shfl_down_sync(~0u, s, o);
    __shared__ int red[32];
    if (lane == 0) red[warp] = s;
    __syncthreads();
    if (warp == 0) {
        int v = red[lane];
#pragma unroll
        for (int o = 16; o > 0; o >>= 1) v += __shfl_down_sync(~0u, v, o);
        if (lane == 0) g_partials[b] = v;
    }
}

__global__ void scan_offsets() {   // 1 warp
    int t = threadIdx.x;
    int p = (t < NBLK) ? g_partials[t] : 0;
    int v = p;
#pragma unroll
    for (int o = 1; o < 32; o <<= 1) {
        int n = __shfl_up_sync(~0u, v, o);
        if (t >= o) v += n;
    }
    if (t < NBLK) g_blockoff[t] = v - p;   // exclusive
}

__global__ void __launch_bounds__(SCAN_BS) scan_final() {
    int b = blockIdx.x, t = threadIdx.x;
    int lane = t & 31, warp = t >> 5;
    int base = b * SCAN_CHUNK + t * 4;
    int d[4];
#pragma unroll
    for (int j = 0; j < 4; j++)
        d[j] = (base + j < NN) ? g_deg[base + j] : 0;
    int s = d[0] + d[1] + d[2] + d[3];
    // inclusive warp scan of per-thread sums
    int v = s;
#pragma unroll
    for (int o = 1; o < 32; o <<= 1) {
        int n = __shfl_up_sync(~0u, v, o);
        if (lane >= o) v += n;
    }
    __shared__ int wsum[32];
    if (lane == 31) wsum[warp] = v;
    __syncthreads();
    if (warp == 0) {
        int w = wsum[lane];
        int wv = w;
#pragma unroll
        for (int o = 1; o < 32; o <<= 1) {
            int n = __shfl_up_sync(~0u, wv, o);
            if (lane >= o) wv += n;
        }
        wsum[lane] = wv - w;  // exclusive
    }
    __syncthreads();
    int run = g_blockoff[b] + wsum[warp] + (v - s);
#pragma unroll
    for (int j = 0; j < 4; j++) {
        int idx = base + j;
        if (idx < NN) {
            g_rowptr[idx] = run;
            g_cursor[idx] = run;
            run += d[j];
            if (idx == NN - 1) g_rowptr[NN] = run;
        }
    }
}

__global__ void fill_kernel(const int* __restrict__ ei, int E) {
    int e = blockIdx.x * blockDim.x + threadIdx.x;
    if (e >= E) return;
    int src = ei[e];
    int dst = ei[E + e];
    int pos = atomicAdd(&g_cursor[dst], 1);
    g_srcs[pos] = src;
}

// ================= layer-1 GEMM: [y1 | z1] = x @ [W1l | W1r] =================
__global__ void __launch_bounds__(128) gemm1_kernel(
    const float* __restrict__ x,
    const float* __restrict__ W1l,
    const float* __restrict__ W1r,
    int n)
{
    __shared__ float sW[IN_DIM][2 * HID];  // 24 KB
    for (int i = threadIdx.x; i < IN_DIM * HID; i += blockDim.x) {
        int k = i / HID, j = i % HID;
        sW[k][j]       = W1l[i];
        sW[k][j + HID] = W1r[i];
    }
    __syncthreads();

    int node = blockIdx.x * blockDim.x + threadIdx.x;
    if (node >= n) return;

    float acc[64];
#pragma unroll
    for (int j = 0; j < 64; j++) acc[j] = 0.f;

    const float4* xr = (const float4*)(x + (size_t)node * IN_DIM);
#pragma unroll 1
    for (int kq = 0; kq < IN_DIM / 4; kq++) {
        float4 xv = __ldg(&xr[kq]);
        float xs[4] = {xv.x, xv.y, xv.z, xv.w};
#pragma unroll
        for (int kk = 0; kk < 4; kk++) {
            float xk = xs[kk];
            const float* wr = sW[kq * 4 + kk];
#pragma unroll
            for (int j = 0; j < 64; j += 4) {
                float4 w = *(const float4*)&wr[j];
                acc[j + 0] += xk * w.x;
                acc[j + 1] += xk * w.y;
                acc[j + 2] += xk * w.z;
                acc[j + 3] += xk * w.w;
            }
        }
    }

    float* y = g_y1 + (size_t)node * HID;
    float* z = g_z1 + (size_t)node * HID;
#pragma unroll
    for (int j = 0; j < HID; j += 4) {
        *(float4*)&y[j] = make_float4(acc[j], acc[j + 1], acc[j + 2], acc[j + 3]);
        *(float4*)&z[j] = make_float4(acc[HID + j], acc[HID + j + 1],
                                      acc[HID + j + 2], acc[HID + j + 3]);
    }
}

// ================= gather layer 1 (fused combine) ===========================
// warp per node; lane k accumulates feature k.
__global__ void __launch_bounds__(256) gather1_kernel(const float* __restrict__ b1) {
    int gtid = blockIdx.x * blockDim.x + threadIdx.x;
    int node = gtid >> 5;
    int lane = gtid & 31;
    if (node >= NN) return;

    int rs = g_rowptr[node];
    int re = g_rowptr[node + 1];

    float acc = 0.f;
    for (int i = rs; i < re; i++) {
        int src = __ldg(&g_srcs[i]);
        acc += __ldg(&g_y1[(size_t)src * HID + lane]);
    }
    float deg = (float)(re - rs);
    float invc = 1.0f / fmaxf(deg, 1.0f);
    if (lane == 0) g_invc[node] = invc;

    float hval = fmaxf(fmaf(acc, invc, g_z1[(size_t)node * HID + lane] + b1[lane]), 0.f);
    g_h[(size_t)node * HID + lane] = hval;
}

// ================= gather layer 2 ===========================================
__global__ void __launch_bounds__(256) gather2_kernel() {
    int gtid = blockIdx.x * blockDim.x + threadIdx.x;
    int node = gtid >> 5;
    int lane = gtid & 31;
    if (node >= NN) return;

    int rs = g_rowptr[node];
    int re = g_rowptr[node + 1];

    float acc = 0.f;
    for (int i = rs; i < re; i++) {
        int src = __ldg(&g_srcs[i]);
        acc += __ldg(&g_h[(size_t)src * HID + lane]);
    }
    g_v[(size_t)node * HID + lane] = acc * g_invc[node];
}

// ================= layer 2: out = v@W2l + h@W2r + b2 ========================
__global__ void __launch_bounds__(128) layer2_kernel(
    const float* __restrict__ W2l,
    const float* __restrict__ W2r,
    const float* __restrict__ b2,
    float* __restrict__ out,
    int n)
{
    __shared__ float sW[2 * HID][OUT_DIM];  // 16 KB; rows 0..31 = W2l
    for (int i = threadIdx.x; i < HID * OUT_DIM; i += blockDim.x) {
        int k = i / OUT_DIM, j = i % OUT_DIM;
        sW[k][j]       = W2l[i];
        sW[k + HID][j] = W2r[i];
    }
    __syncthreads();

    int node = blockIdx.x * blockDim.x + threadIdx.x;
    if (node >= n) return;

    float v[64];
#pragma unroll
    for (int k = 0; k < HID; k += 4) {
        float4 a = *(const float4*)&g_v[(size_t)node * HID + k];
        v[k + 0] = a.x; v[k + 1] = a.y; v[k + 2] = a.z; v[k + 3] = a.w;
        float4 hh = *(const float4*)&g_h[(size_t)node * HID + k];
        v[HID + k + 0] = hh.x; v[HID + k + 1] = hh.y;
        v[HID + k + 2] = hh.z; v[HID + k + 3] = hh.w;
    }

#pragma unroll 1
    for (int j = 0; j < OUT_DIM; j += 4) {
        float4 bb = *(const float4*)&b2[j];
        float a0 = bb.x, a1 = bb.y, a2 = bb.z, a3 = bb.w;
#pragma unroll
        for (int k = 0; k < 64; k++) {
            float4 w = *(const float4*)&sW[k][j];
            a0 += v[k] * w.x;
            a1 += v[k] * w.y;
            a2 += v[k] * w.z;
            a3 += v[k] * w.w;
        }
        *(float4*)&out[(size_t)node * OUT_DIM + j] = make_float4(a0, a1, a2, a3);
    }
}

// ================= launch ===================================================
extern "C" void kernel_launch(void* const* d_in, const int* in_sizes, int n_in,
                              void* d_out, int out_size)
{
    const float* x   = (const float*)d_in[0];
    const int*   ei  = (const int*)d_in[1];   // int32 (JAX x64 disabled)
    const float* W1l = (const float*)d_in[2];
    const float* W1r = (const float*)d_in[3];
    const float* b1  = (const float*)d_in[4];
    const float* W2l = (const float*)d_in[5];
    const float* W2r = (const float*)d_in[6];
    const float* b2  = (const float*)d_in[7];
    float*       out = (float*)d_out;

    int n = in_sizes[0] / IN_DIM;   // 50000
    int E = in_sizes[1] / 2;        // 800000

    // --- CSR build ---
    zero_deg<<<(NN + 1023) / 1024, 1024>>>();
    hist_kernel<<<(E + 511) / 512, 512>>>(ei + E, E);
    scan_partial<<<NBLK, SCAN_BS>>>();
    scan_offsets<<<1, 32>>>();
    scan_final<<<NBLK, SCAN_BS>>>();
    fill_kernel<<<(E + 511) / 512, 512>>>(ei, E);

    // --- layer 1 ---
    gemm1_kernel<<<(n + 127) / 128, 128>>>(x, W1l, W1r, n);
    {
        long long work = (long long)NN * 32;
        gather1_kernel<<<(int)((work + 255) / 256), 256>>>(b1);
    }

    // --- layer 2 ---
    {
        long long work = (long long)NN * 32;
        gather2_kernel<<<(int)((work + 255) / 256), 256>>>();
    }
    layer2_kernel<<<(n + 127) / 128, 128>>>(W2l, W2r, b2, out, n);
}